// round 1
// baseline (speedup 1.0000x reference)
#include <cuda_runtime.h>
#include <math.h>

#define T_TOK 2048
#define HDIM  1024
#define FDIM  512
#define NE    32
#define TOPK  4

// ---------------- scratch (static __device__ globals; no allocation) ----------------
__device__ int   g_cnt[NE];
__device__ int   g_base[NE];
__device__ int   g_btok[NE * T_TOK];
__device__ float g_bw  [NE * T_TOK];
__device__ int   g_pe  [T_TOK * TOPK];   // per (token,k): expert id
__device__ int   g_pp  [T_TOK * TOPK];   // per (token,k): position in expert bucket
__device__ float g_hbuf[(size_t)T_TOK * TOPK * FDIM];   // 16 MB: relu(g)*u per slot
__device__ float g_ybuf[(size_t)T_TOK * TOPK * HDIM];   // 32 MB: weighted down-proj per slot

// ---------------- router GEMM: logits[T,E] = x_r @ w_router^T ----------------
// block: 64 tokens x 32 experts, 256 threads, thread = 8 tokens x 1 expert
__global__ void router_gemm(const float* __restrict__ xr, const float* __restrict__ wr,
                            float* __restrict__ logits) {
    __shared__ float Xs[16][68];
    __shared__ float Ws[16][36];
    int tid = threadIdx.x;
    int t0  = blockIdx.x * 64;
    int tx = tid & 31, ty = tid >> 5;
    float acc[8];
#pragma unroll
    for (int j = 0; j < 8; j++) acc[j] = 0.f;
    int mL = tid >> 2, ksL = tid & 3;
    for (int k0 = 0; k0 < HDIM; k0 += 16) {
        float4 v = *(const float4*)(xr + (size_t)(t0 + mL) * HDIM + k0 + ksL * 4);
        Xs[ksL*4+0][mL] = v.x; Xs[ksL*4+1][mL] = v.y;
        Xs[ksL*4+2][mL] = v.z; Xs[ksL*4+3][mL] = v.w;
        if (tid < 128) {
            int n = tid >> 2, ks = tid & 3;
            float4 w = *(const float4*)(wr + (size_t)n * HDIM + k0 + ks * 4);
            Ws[ks*4+0][n] = w.x; Ws[ks*4+1][n] = w.y;
            Ws[ks*4+2][n] = w.z; Ws[ks*4+3][n] = w.w;
        }
        __syncthreads();
#pragma unroll
        for (int kk = 0; kk < 16; kk++) {
            float b = Ws[kk][tx];
            float4 a0 = *(const float4*)&Xs[kk][ty*8];
            float4 a1 = *(const float4*)&Xs[kk][ty*8+4];
            acc[0] += a0.x*b; acc[1] += a0.y*b; acc[2] += a0.z*b; acc[3] += a0.w*b;
            acc[4] += a1.x*b; acc[5] += a1.y*b; acc[6] += a1.z*b; acc[7] += a1.w*b;
        }
        __syncthreads();
    }
#pragma unroll
    for (int j = 0; j < 8; j++)
        logits[(size_t)(t0 + ty*8 + j) * NE + tx] = acc[j];
}

// ---------------- zero counters ----------------
__global__ void zero_cnt() {
    if (threadIdx.x < NE) g_cnt[threadIdx.x] = 0;
}

// ---------------- top-4 + softmax + bucket push ----------------
__global__ void topk_kernel(const float* __restrict__ logits) {
    int t = blockIdx.x * blockDim.x + threadIdx.x;
    if (t >= T_TOK) return;
    float v[NE];
#pragma unroll
    for (int e = 0; e < NE; e++) v[e] = logits[(size_t)t * NE + e];
    float val[TOPK]; int sel[TOPK];
#pragma unroll
    for (int kk = 0; kk < TOPK; kk++) {
        float best = -INFINITY; int bi = 0;
#pragma unroll
        for (int e = 0; e < NE; e++)
            if (v[e] > best) { best = v[e]; bi = e; }
        val[kk] = best; sel[kk] = bi; v[bi] = -INFINITY;
    }
    float mx = val[0];
    float w[TOPK], s = 0.f;
#pragma unroll
    for (int kk = 0; kk < TOPK; kk++) { w[kk] = expf(val[kk] - mx); s += w[kk]; }
    float inv = 1.f / s;
#pragma unroll
    for (int kk = 0; kk < TOPK; kk++) {
        int e = sel[kk];
        int pos = atomicAdd(&g_cnt[e], 1);
        g_btok[e * T_TOK + pos] = t;
        g_bw  [e * T_TOK + pos] = w[kk] * inv;
        g_pe[t * TOPK + kk] = e;
        g_pp[t * TOPK + kk] = pos;
    }
}

// ---------------- exclusive prefix over 32 counts ----------------
__global__ void prefix_kernel() {
    if (threadIdx.x == 0) {
        int s = 0;
        for (int e = 0; e < NE; e++) { g_base[e] = s; s += g_cnt[e]; }
    }
}

// ---------------- gate/up GEMM: per expert, h = relu(X Wg^T) * (X Wu^T) ----------------
// block tile: 128 tokens x 64 F-cols, BK=16; thread tile 8x4 (dual accum G,U)
__global__ void __launch_bounds__(256, 2) gateup_kernel(
        const float* __restrict__ hid, const float* __restrict__ wg,
        const float* __restrict__ wu) {
    int e   = blockIdx.z;
    int cnt = g_cnt[e];
    int m0  = blockIdx.y * 128;
    if (m0 >= cnt) return;
    int f0 = blockIdx.x * 64;

    __shared__ float Xs[16][132];
    __shared__ float Gs[16][68];
    __shared__ float Us[16][68];

    int tid = threadIdx.x;
    const int* btok = g_btok + e * T_TOK;
    int mL1 = tid >> 2;           // 0..63
    int mL2 = 64 + mL1;
    int ksL = tid & 3;
    int tok1 = btok[min(m0 + mL1, cnt - 1)];
    int tok2 = btok[min(m0 + mL2, cnt - 1)];
    const float* wge = wg + (size_t)e * FDIM * HDIM;
    const float* wue = wu + (size_t)e * FDIM * HDIM;
    int nL = tid >> 2;            // 0..63

    float accG[8][4], accU[8][4];
#pragma unroll
    for (int i = 0; i < 8; i++)
#pragma unroll
        for (int j = 0; j < 4; j++) { accG[i][j] = 0.f; accU[i][j] = 0.f; }

    int tx = tid & 15, ty = tid >> 4;

    for (int k0 = 0; k0 < HDIM; k0 += 16) {
        float4 x1 = *(const float4*)(hid + (size_t)tok1 * HDIM + k0 + ksL * 4);
        float4 x2 = *(const float4*)(hid + (size_t)tok2 * HDIM + k0 + ksL * 4);
        float4 gv = *(const float4*)(wge + (size_t)(f0 + nL) * HDIM + k0 + ksL * 4);
        float4 uv = *(const float4*)(wue + (size_t)(f0 + nL) * HDIM + k0 + ksL * 4);
        Xs[ksL*4+0][mL1] = x1.x; Xs[ksL*4+1][mL1] = x1.y;
        Xs[ksL*4+2][mL1] = x1.z; Xs[ksL*4+3][mL1] = x1.w;
        Xs[ksL*4+0][mL2] = x2.x; Xs[ksL*4+1][mL2] = x2.y;
        Xs[ksL*4+2][mL2] = x2.z; Xs[ksL*4+3][mL2] = x2.w;
        Gs[ksL*4+0][nL] = gv.x; Gs[ksL*4+1][nL] = gv.y;
        Gs[ksL*4+2][nL] = gv.z; Gs[ksL*4+3][nL] = gv.w;
        Us[ksL*4+0][nL] = uv.x; Us[ksL*4+1][nL] = uv.y;
        Us[ksL*4+2][nL] = uv.z; Us[ksL*4+3][nL] = uv.w;
        __syncthreads();
#pragma unroll
        for (int kk = 0; kk < 16; kk++) {
            float4 a0 = *(const float4*)&Xs[kk][ty*8];
            float4 a1 = *(const float4*)&Xs[kk][ty*8+4];
            float4 bg = *(const float4*)&Gs[kk][tx*4];
            float4 bu = *(const float4*)&Us[kk][tx*4];
            float a[8] = {a0.x, a0.y, a0.z, a0.w, a1.x, a1.y, a1.z, a1.w};
#pragma unroll
            for (int i = 0; i < 8; i++) {
                accG[i][0] += a[i]*bg.x; accG[i][1] += a[i]*bg.y;
                accG[i][2] += a[i]*bg.z; accG[i][3] += a[i]*bg.w;
                accU[i][0] += a[i]*bu.x; accU[i][1] += a[i]*bu.y;
                accU[i][2] += a[i]*bu.z; accU[i][3] += a[i]*bu.w;
            }
        }
        __syncthreads();
    }
    int base = g_base[e];
#pragma unroll
    for (int i = 0; i < 8; i++) {
        int m = m0 + ty*8 + i;
        if (m < cnt) {
            float4 hv;
            hv.x = fmaxf(accG[i][0], 0.f) * accU[i][0];
            hv.y = fmaxf(accG[i][1], 0.f) * accU[i][1];
            hv.z = fmaxf(accG[i][2], 0.f) * accU[i][2];
            hv.w = fmaxf(accG[i][3], 0.f) * accU[i][3];
            *(float4*)(g_hbuf + (size_t)(base + m) * FDIM + f0 + tx*4) = hv;
        }
    }
}

// ---------------- down GEMM: y = (h Wd^T) * routing_weight ----------------
__global__ void __launch_bounds__(256, 2) down_kernel(const float* __restrict__ wd) {
    int e   = blockIdx.z;
    int cnt = g_cnt[e];
    int m0  = blockIdx.y * 128;
    if (m0 >= cnt) return;
    int h0 = blockIdx.x * 64;

    __shared__ float Hs[16][132];
    __shared__ float Ds[16][68];

    int tid  = threadIdx.x;
    int base = g_base[e];
    int mL1 = tid >> 2, mL2 = 64 + mL1, ksL = tid & 3;
    int r1 = base + min(m0 + mL1, cnt - 1);
    int r2 = base + min(m0 + mL2, cnt - 1);
    const float* wde = wd + (size_t)e * HDIM * FDIM;
    int nL = tid >> 2;

    float acc[8][4];
#pragma unroll
    for (int i = 0; i < 8; i++)
#pragma unroll
        for (int j = 0; j < 4; j++) acc[i][j] = 0.f;

    int tx = tid & 15, ty = tid >> 4;

    for (int k0 = 0; k0 < FDIM; k0 += 16) {
        float4 x1 = *(const float4*)(g_hbuf + (size_t)r1 * FDIM + k0 + ksL * 4);
        float4 x2 = *(const float4*)(g_hbuf + (size_t)r2 * FDIM + k0 + ksL * 4);
        float4 dv = *(const float4*)(wde + (size_t)(h0 + nL) * FDIM + k0 + ksL * 4);
        Hs[ksL*4+0][mL1] = x1.x; Hs[ksL*4+1][mL1] = x1.y;
        Hs[ksL*4+2][mL1] = x1.z; Hs[ksL*4+3][mL1] = x1.w;
        Hs[ksL*4+0][mL2] = x2.x; Hs[ksL*4+1][mL2] = x2.y;
        Hs[ksL*4+2][mL2] = x2.z; Hs[ksL*4+3][mL2] = x2.w;
        Ds[ksL*4+0][nL] = dv.x; Ds[ksL*4+1][nL] = dv.y;
        Ds[ksL*4+2][nL] = dv.z; Ds[ksL*4+3][nL] = dv.w;
        __syncthreads();
#pragma unroll
        for (int kk = 0; kk < 16; kk++) {
            float4 a0 = *(const float4*)&Hs[kk][ty*8];
            float4 a1 = *(const float4*)&Hs[kk][ty*8+4];
            float4 bd = *(const float4*)&Ds[kk][tx*4];
            float a[8] = {a0.x, a0.y, a0.z, a0.w, a1.x, a1.y, a1.z, a1.w};
#pragma unroll
            for (int i = 0; i < 8; i++) {
                acc[i][0] += a[i]*bd.x; acc[i][1] += a[i]*bd.y;
                acc[i][2] += a[i]*bd.z; acc[i][3] += a[i]*bd.w;
            }
        }
        __syncthreads();
    }
    const float* bw = g_bw + e * T_TOK;
#pragma unroll
    for (int i = 0; i < 8; i++) {
        int m = m0 + ty*8 + i;
        if (m < cnt) {
            float wgt = bw[m];
            float4 yv = make_float4(acc[i][0]*wgt, acc[i][1]*wgt,
                                    acc[i][2]*wgt, acc[i][3]*wgt);
            *(float4*)(g_ybuf + (size_t)(base + m) * HDIM + h0 + tx*4) = yv;
        }
    }
}

// ---------------- combine: out[t] = sum over the token's 4 slots ----------------
__global__ void combine_kernel(float* __restrict__ out) {
    int t   = blockIdx.x;
    int tid = threadIdx.x;       // 256 threads, 4 floats each
    int sl[TOPK];
#pragma unroll
    for (int kk = 0; kk < TOPK; kk++)
        sl[kk] = g_base[g_pe[t*TOPK + kk]] + g_pp[t*TOPK + kk];
    int h = tid * 4;
    float4 a = *(const float4*)(g_ybuf + (size_t)sl[0] * HDIM + h);
    float4 b = *(const float4*)(g_ybuf + (size_t)sl[1] * HDIM + h);
    float4 c = *(const float4*)(g_ybuf + (size_t)sl[2] * HDIM + h);
    float4 d = *(const float4*)(g_ybuf + (size_t)sl[3] * HDIM + h);
    float4 r;
    r.x = a.x + b.x + c.x + d.x;
    r.y = a.y + b.y + c.y + d.y;
    r.z = a.z + b.z + c.z + d.z;
    r.w = a.w + b.w + c.w + d.w;
    *(float4*)(out + (size_t)t * HDIM + h) = r;
}

// ---------------- launch ----------------
extern "C" void kernel_launch(void* const* d_in, const int* in_sizes, int n_in,
                              void* d_out, int out_size) {
    const float* router_input = (const float*)d_in[0];
    const float* hidden       = (const float*)d_in[1];
    const float* w_router     = (const float*)d_in[2];
    const float* w_gate       = (const float*)d_in[3];
    const float* w_up         = (const float*)d_in[4];
    const float* w_down       = (const float*)d_in[5];
    float* out    = (float*)d_out;                       // [T, H]
    float* logits = out + (size_t)T_TOK * HDIM;          // [T, E]

    zero_cnt<<<1, 32>>>();
    router_gemm<<<T_TOK / 64, 256>>>(router_input, w_router, logits);
    topk_kernel<<<T_TOK / 256, 256>>>(logits);
    prefix_kernel<<<1, 32>>>();
    gateup_kernel<<<dim3(FDIM / 64, (T_TOK + 127) / 128, NE), 256>>>(hidden, w_gate, w_up);
    down_kernel<<<dim3(HDIM / 64, (T_TOK + 127) / 128, NE), 256>>>(w_down);
    combine_kernel<<<T_TOK, 256>>>(out);
}

// round 4
// speedup vs baseline: 1.7382x; 1.7382x over previous
#include <cuda_runtime.h>
#include <cuda_bf16.h>
#include <math.h>
#include <stdint.h>

#define T_TOK 2048
#define HDIM  1024
#define FDIM  512
#define NE    32
#define TOPK  4
#define SLOTS (T_TOK * TOPK)

// ---------------- scratch ----------------
__device__ int   g_cnt[NE];
__device__ int   g_base[NE];
__device__ int   g_btok[NE * T_TOK];
__device__ float g_bw  [NE * T_TOK];
__device__ int   g_pe  [T_TOK * TOPK];
__device__ int   g_pp  [T_TOK * TOPK];
__device__ __nv_bfloat16 g_hhi[(size_t)SLOTS * FDIM];   // 8 MB
__device__ __nv_bfloat16 g_hlo[(size_t)SLOTS * FDIM];   // 8 MB
__device__ float g_ybuf[(size_t)SLOTS * HDIM];          // 32 MB

// ---------------- helpers ----------------
__device__ __forceinline__ void mma16816(float* d, const uint32_t* a, const uint32_t* b) {
    asm volatile(
        "mma.sync.aligned.m16n8k16.row.col.f32.bf16.bf16.f32 "
        "{%0,%1,%2,%3}, {%4,%5,%6,%7}, {%8,%9}, {%0,%1,%2,%3};\n"
        : "+f"(d[0]), "+f"(d[1]), "+f"(d[2]), "+f"(d[3])
        : "r"(a[0]), "r"(a[1]), "r"(a[2]), "r"(a[3]), "r"(b[0]), "r"(b[1]));
}

__device__ __forceinline__ void split2(float a, float b, uint32_t& h, uint32_t& l) {
    __nv_bfloat162 hh = __floats2bfloat162_rn(a, b);
    float2 hf = __bfloat1622float2(hh);
    __nv_bfloat162 ll = __floats2bfloat162_rn(a - hf.x, b - hf.y);
    h = *reinterpret_cast<uint32_t*>(&hh);
    l = *reinterpret_cast<uint32_t*>(&ll);
}

// split 8 fp32 -> two uint4 (bf16 hi, bf16 lo)
__device__ __forceinline__ void split8(const float* x, uint4& hv, uint4& lv) {
    uint32_t h[4], l[4];
#pragma unroll
    for (int i = 0; i < 4; i++) split2(x[2*i], x[2*i+1], h[i], l[i]);
    hv = make_uint4(h[0], h[1], h[2], h[3]);
    lv = make_uint4(l[0], l[1], l[2], l[3]);
}

// ---------------- router GEMM ----------------
__global__ void router_gemm(const float* __restrict__ xr, const float* __restrict__ wr,
                            float* __restrict__ logits) {
    __shared__ float Xs[16][68];
    __shared__ float Ws[16][36];
    int tid = threadIdx.x;
    int t0  = blockIdx.x * 64;
    int tx = tid & 31, ty = tid >> 5;
    float acc[8];
#pragma unroll
    for (int j = 0; j < 8; j++) acc[j] = 0.f;
    int mL = tid >> 2, ksL = tid & 3;
    for (int k0 = 0; k0 < HDIM; k0 += 16) {
        float4 v = *(const float4*)(xr + (size_t)(t0 + mL) * HDIM + k0 + ksL * 4);
        Xs[ksL*4+0][mL] = v.x; Xs[ksL*4+1][mL] = v.y;
        Xs[ksL*4+2][mL] = v.z; Xs[ksL*4+3][mL] = v.w;
        if (tid < 128) {
            int n = tid >> 2, ks = tid & 3;
            float4 w = *(const float4*)(wr + (size_t)n * HDIM + k0 + ks * 4);
            Ws[ks*4+0][n] = w.x; Ws[ks*4+1][n] = w.y;
            Ws[ks*4+2][n] = w.z; Ws[ks*4+3][n] = w.w;
        }
        __syncthreads();
#pragma unroll
        for (int kk = 0; kk < 16; kk++) {
            float b = Ws[kk][tx];
            float4 a0 = *(const float4*)&Xs[kk][ty*8];
            float4 a1 = *(const float4*)&Xs[kk][ty*8+4];
            acc[0] += a0.x*b; acc[1] += a0.y*b; acc[2] += a0.z*b; acc[3] += a0.w*b;
            acc[4] += a1.x*b; acc[5] += a1.y*b; acc[6] += a1.z*b; acc[7] += a1.w*b;
        }
        __syncthreads();
    }
#pragma unroll
    for (int j = 0; j < 8; j++)
        logits[(size_t)(t0 + ty*8 + j) * NE + tx] = acc[j];
}

__global__ void zero_cnt() { if (threadIdx.x < NE) g_cnt[threadIdx.x] = 0; }

__global__ void topk_kernel(const float* __restrict__ logits) {
    int t = blockIdx.x * blockDim.x + threadIdx.x;
    if (t >= T_TOK) return;
    float v[NE];
#pragma unroll
    for (int e = 0; e < NE; e++) v[e] = logits[(size_t)t * NE + e];
    float val[TOPK]; int sel[TOPK];
#pragma unroll
    for (int kk = 0; kk < TOPK; kk++) {
        float best = -INFINITY; int bi = 0;
#pragma unroll
        for (int e = 0; e < NE; e++)
            if (v[e] > best) { best = v[e]; bi = e; }
        val[kk] = best; sel[kk] = bi; v[bi] = -INFINITY;
    }
    float mx = val[0];
    float w[TOPK], s = 0.f;
#pragma unroll
    for (int kk = 0; kk < TOPK; kk++) { w[kk] = expf(val[kk] - mx); s += w[kk]; }
    float inv = 1.f / s;
#pragma unroll
    for (int kk = 0; kk < TOPK; kk++) {
        int e = sel[kk];
        int pos = atomicAdd(&g_cnt[e], 1);
        g_btok[e * T_TOK + pos] = t;
        g_bw  [e * T_TOK + pos] = w[kk] * inv;
        g_pe[t * TOPK + kk] = e;
        g_pp[t * TOPK + kk] = pos;
    }
}

__global__ void prefix_kernel() {
    if (threadIdx.x == 0) {
        int s = 0;
        for (int e = 0; e < NE; e++) { g_base[e] = s; s += g_cnt[e]; }
    }
}

// ================= gate/up HMMA kernel =================
// CTA: 128 tokens x 64 F-cols. 8 warps: wm = wid&3 (M), wn = wid>>2 (N), 32x32 warp tile.
// BK=32, split-bf16 3-pass. SMEM rows padded to 40 bf16 (80B, 16B-aligned, conflict-free).
#define PADK 40
__global__ void __launch_bounds__(256) gateup_mma(
        const float* __restrict__ hid, const float* __restrict__ wg,
        const float* __restrict__ wu) {
    int e   = blockIdx.z;
    int cnt = g_cnt[e];
    int m0  = blockIdx.y * 128;
    if (m0 >= cnt) return;
    int f0 = blockIdx.x * 64;

    __shared__ __nv_bfloat16 sXh[128][PADK], sXl[128][PADK];
    __shared__ __nv_bfloat16 sGh[64][PADK],  sGl[64][PADK];
    __shared__ __nv_bfloat16 sUh[64][PADK],  sUl[64][PADK];

    int tid = threadIdx.x, wid = tid >> 5, lane = tid & 31;
    int wm = wid & 3, wn = wid >> 1 & 0 ? 0 : (wid >> 2);  // wn = wid>>2
    int g = lane >> 2, q = lane & 3;

    // loader roles
    int xrow = tid >> 1, xseg = tid & 1;                 // X: 128 rows, 2 segs of 16
    int tokL = g_btok[e * T_TOK + min(m0 + xrow, cnt - 1)];
    const float* xsrc = hid + (size_t)tokL * HDIM;
    int wrow = tid >> 2, wq = tid & 3;                   // W: 64 rows, 4 segs of 8
    const float* gsrc = wg + (size_t)e * FDIM * HDIM + (size_t)(f0 + wrow) * HDIM;
    const float* usrc = wu + (size_t)e * FDIM * HDIM + (size_t)(f0 + wrow) * HDIM;

    float accG[2][4][4] = {}, accU[2][4][4] = {};

    for (int k0 = 0; k0 < HDIM; k0 += 32) {
        // --- stage + convert ---
        {
            const float* s = xsrc + k0 + xseg * 16;
            float x[8]; uint4 hv, lv;
            *(float4*)&x[0] = *(const float4*)(s);
            *(float4*)&x[4] = *(const float4*)(s + 4);
            split8(x, hv, lv);
            *(uint4*)&sXh[xrow][xseg*16]   = hv;
            *(uint4*)&sXl[xrow][xseg*16]   = lv;
            *(float4*)&x[0] = *(const float4*)(s + 8);
            *(float4*)&x[4] = *(const float4*)(s + 12);
            split8(x, hv, lv);
            *(uint4*)&sXh[xrow][xseg*16+8] = hv;
            *(uint4*)&sXl[xrow][xseg*16+8] = lv;
        }
        {
            float x[8]; uint4 hv, lv;
            const float* s = gsrc + k0 + wq * 8;
            *(float4*)&x[0] = *(const float4*)(s);
            *(float4*)&x[4] = *(const float4*)(s + 4);
            split8(x, hv, lv);
            *(uint4*)&sGh[wrow][wq*8] = hv;
            *(uint4*)&sGl[wrow][wq*8] = lv;
            s = usrc + k0 + wq * 8;
            *(float4*)&x[0] = *(const float4*)(s);
            *(float4*)&x[4] = *(const float4*)(s + 4);
            split8(x, hv, lv);
            *(uint4*)&sUh[wrow][wq*8] = hv;
            *(uint4*)&sUl[wrow][wq*8] = lv;
        }
        __syncthreads();

        // --- compute ---
#pragma unroll
        for (int kt = 0; kt < 2; kt++) {
            int kc = kt * 16 + 2 * q;
            uint32_t axh[2][4], axl[2][4];
#pragma unroll
            for (int mt = 0; mt < 2; mt++) {
                int r = wm * 32 + mt * 16 + g;
                axh[mt][0] = *(const uint32_t*)&sXh[r][kc];
                axh[mt][1] = *(const uint32_t*)&sXh[r+8][kc];
                axh[mt][2] = *(const uint32_t*)&sXh[r][kc+8];
                axh[mt][3] = *(const uint32_t*)&sXh[r+8][kc+8];
                axl[mt][0] = *(const uint32_t*)&sXl[r][kc];
                axl[mt][1] = *(const uint32_t*)&sXl[r+8][kc];
                axl[mt][2] = *(const uint32_t*)&sXl[r][kc+8];
                axl[mt][3] = *(const uint32_t*)&sXl[r+8][kc+8];
            }
#pragma unroll
            for (int nt = 0; nt < 4; nt++) {
                int br = wn * 32 + nt * 8 + g;
                uint32_t bgh[2] = {*(const uint32_t*)&sGh[br][kc], *(const uint32_t*)&sGh[br][kc+8]};
                uint32_t bgl[2] = {*(const uint32_t*)&sGl[br][kc], *(const uint32_t*)&sGl[br][kc+8]};
                uint32_t buh[2] = {*(const uint32_t*)&sUh[br][kc], *(const uint32_t*)&sUh[br][kc+8]};
                uint32_t bul[2] = {*(const uint32_t*)&sUl[br][kc], *(const uint32_t*)&sUl[br][kc+8]};
#pragma unroll
                for (int mt = 0; mt < 2; mt++) {
                    mma16816(accG[mt][nt], axh[mt], bgh);
                    mma16816(accG[mt][nt], axl[mt], bgh);
                    mma16816(accG[mt][nt], axh[mt], bgl);
                    mma16816(accU[mt][nt], axh[mt], buh);
                    mma16816(accU[mt][nt], axl[mt], buh);
                    mma16816(accU[mt][nt], axh[mt], bul);
                }
            }
        }
        __syncthreads();
    }

    // --- epilogue: h = relu(G)*U, write bf16 hi/lo ---
    int base = g_base[e];
#pragma unroll
    for (int mt = 0; mt < 2; mt++) {
        int lm0 = wm * 32 + mt * 16 + g;
#pragma unroll
        for (int nt = 0; nt < 4; nt++) {
            int c = f0 + wn * 32 + nt * 8 + 2 * q;
            float* Gd = accG[mt][nt];
            float* Ud = accU[mt][nt];
            float v0 = fmaxf(Gd[0], 0.f) * Ud[0];
            float v1 = fmaxf(Gd[1], 0.f) * Ud[1];
            float v2 = fmaxf(Gd[2], 0.f) * Ud[2];
            float v3 = fmaxf(Gd[3], 0.f) * Ud[3];
            uint32_t h01, l01, h23, l23;
            split2(v0, v1, h01, l01);
            split2(v2, v3, h23, l23);
            int m = m0 + lm0;
            if (m < cnt) {
                size_t slot = (size_t)base + m;
                *(uint32_t*)(g_hhi + slot * FDIM + c) = h01;
                *(uint32_t*)(g_hlo + slot * FDIM + c) = l01;
            }
            if (m + 8 < cnt) {
                size_t slot = (size_t)base + m + 8;
                *(uint32_t*)(g_hhi + slot * FDIM + c) = h23;
                *(uint32_t*)(g_hlo + slot * FDIM + c) = l23;
            }
        }
    }
}

// ================= down HMMA kernel =================
// CTA: 128 slots x 64 H-cols, K=FDIM in 16 chunks of 32.
__global__ void __launch_bounds__(256) down_mma(const float* __restrict__ wd) {
    int e   = blockIdx.z;
    int cnt = g_cnt[e];
    int m0  = blockIdx.y * 128;
    if (m0 >= cnt) return;
    int h0 = blockIdx.x * 64;

    __shared__ __nv_bfloat16 sXh[128][PADK], sXl[128][PADK];
    __shared__ __nv_bfloat16 sWh[64][PADK],  sWl[64][PADK];

    int tid = threadIdx.x, wid = tid >> 5, lane = tid & 31;
    int wm = wid & 3, wn = wid >> 2;
    int g = lane >> 2, q = lane & 3;
    int base = g_base[e];

    int xrow = tid >> 1, xseg = tid & 1;
    size_t slotR = (size_t)base + min(m0 + xrow, cnt - 1);
    const __nv_bfloat16* xhs = g_hhi + slotR * FDIM;
    const __nv_bfloat16* xls = g_hlo + slotR * FDIM;
    int wrow = tid >> 2, wq = tid & 3;
    const float* wsrc = wd + (size_t)e * HDIM * FDIM + (size_t)(h0 + wrow) * FDIM;

    float acc[2][4][4] = {};

    for (int k0 = 0; k0 < FDIM; k0 += 32) {
        {
            int c = k0 + xseg * 16;
            *(uint4*)&sXh[xrow][xseg*16]   = *(const uint4*)(xhs + c);
            *(uint4*)&sXh[xrow][xseg*16+8] = *(const uint4*)(xhs + c + 8);
            *(uint4*)&sXl[xrow][xseg*16]   = *(const uint4*)(xls + c);
            *(uint4*)&sXl[xrow][xseg*16+8] = *(const uint4*)(xls + c + 8);
        }
        {
            float x[8]; uint4 hv, lv;
            const float* s = wsrc + k0 + wq * 8;
            *(float4*)&x[0] = *(const float4*)(s);
            *(float4*)&x[4] = *(const float4*)(s + 4);
            split8(x, hv, lv);
            *(uint4*)&sWh[wrow][wq*8] = hv;
            *(uint4*)&sWl[wrow][wq*8] = lv;
        }
        __syncthreads();

#pragma unroll
        for (int kt = 0; kt < 2; kt++) {
            int kc = kt * 16 + 2 * q;
            uint32_t axh[2][4], axl[2][4];
#pragma unroll
            for (int mt = 0; mt < 2; mt++) {
                int r = wm * 32 + mt * 16 + g;
                axh[mt][0] = *(const uint32_t*)&sXh[r][kc];
                axh[mt][1] = *(const uint32_t*)&sXh[r+8][kc];
                axh[mt][2] = *(const uint32_t*)&sXh[r][kc+8];
                axh[mt][3] = *(const uint32_t*)&sXh[r+8][kc+8];
                axl[mt][0] = *(const uint32_t*)&sXl[r][kc];
                axl[mt][1] = *(const uint32_t*)&sXl[r+8][kc];
                axl[mt][2] = *(const uint32_t*)&sXl[r][kc+8];
                axl[mt][3] = *(const uint32_t*)&sXl[r+8][kc+8];
            }
#pragma unroll
            for (int nt = 0; nt < 4; nt++) {
                int br = wn * 32 + nt * 8 + g;
                uint32_t bwh[2] = {*(const uint32_t*)&sWh[br][kc], *(const uint32_t*)&sWh[br][kc+8]};
                uint32_t bwl[2] = {*(const uint32_t*)&sWl[br][kc], *(const uint32_t*)&sWl[br][kc+8]};
#pragma unroll
                for (int mt = 0; mt < 2; mt++) {
                    mma16816(acc[mt][nt], axh[mt], bwh);
                    mma16816(acc[mt][nt], axl[mt], bwh);
                    mma16816(acc[mt][nt], axh[mt], bwl);
                }
            }
        }
        __syncthreads();
    }

    // --- epilogue: y = acc * routing weight ---
#pragma unroll
    for (int mt = 0; mt < 2; mt++) {
        int lm0 = wm * 32 + mt * 16 + g;
        int m = m0 + lm0;
        float w0 = (m     < cnt) ? g_bw[e * T_TOK + m]     : 0.f;
        float w1 = (m + 8 < cnt) ? g_bw[e * T_TOK + m + 8] : 0.f;
#pragma unroll
        for (int nt = 0; nt < 4; nt++) {
            int c = h0 + wn * 32 + nt * 8 + 2 * q;
            float* D = acc[mt][nt];
            if (m < cnt) {
                float* py = g_ybuf + ((size_t)base + m) * HDIM + c;
                py[0] = D[0] * w0; py[1] = D[1] * w0;
            }
            if (m + 8 < cnt) {
                float* py = g_ybuf + ((size_t)base + m + 8) * HDIM + c;
                py[0] = D[2] * w1; py[1] = D[3] * w1;
            }
        }
    }
}

// ---------------- combine ----------------
__global__ void combine_kernel(float* __restrict__ out) {
    int t   = blockIdx.x;
    int tid = threadIdx.x;
    int sl[TOPK];
#pragma unroll
    for (int kk = 0; kk < TOPK; kk++)
        sl[kk] = g_base[g_pe[t*TOPK + kk]] + g_pp[t*TOPK + kk];
    int h = tid * 4;
    float4 a = *(const float4*)(g_ybuf + (size_t)sl[0] * HDIM + h);
    float4 b = *(const float4*)(g_ybuf + (size_t)sl[1] * HDIM + h);
    float4 c = *(const float4*)(g_ybuf + (size_t)sl[2] * HDIM + h);
    float4 d = *(const float4*)(g_ybuf + (size_t)sl[3] * HDIM + h);
    float4 r;
    r.x = a.x + b.x + c.x + d.x;
    r.y = a.y + b.y + c.y + d.y;
    r.z = a.z + b.z + c.z + d.z;
    r.w = a.w + b.w + c.w + d.w;
    *(float4*)(out + (size_t)t * HDIM + h) = r;
}

// ---------------- launch ----------------
extern "C" void kernel_launch(void* const* d_in, const int* in_sizes, int n_in,
                              void* d_out, int out_size) {
    const float* router_input = (const float*)d_in[0];
    const float* hidden       = (const float*)d_in[1];
    const float* w_router     = (const float*)d_in[2];
    const float* w_gate       = (const float*)d_in[3];
    const float* w_up         = (const float*)d_in[4];
    const float* w_down       = (const float*)d_in[5];
    float* out    = (float*)d_out;
    float* logits = out + (size_t)T_TOK * HDIM;

    zero_cnt<<<1, 32>>>();
    router_gemm<<<T_TOK / 64, 256>>>(router_input, w_router, logits);
    topk_kernel<<<T_TOK / 256, 256>>>(logits);
    prefix_kernel<<<1, 32>>>();
    gateup_mma<<<dim3(FDIM / 64, T_TOK / 128, NE), 256>>>(hidden, w_gate, w_up);
    down_mma<<<dim3(HDIM / 64, T_TOK / 128, NE), 256>>>(w_down);
    combine_kernel<<<T_TOK, 256>>>(out);
}